// round 2
// baseline (speedup 1.0000x reference)
#include <cuda_runtime.h>
#include <math.h>

// Problem constants (fixed by the dataset)
#define T_TOK  4096     // B * S
#define HID    4096     // hidden
#define SEQ    1024     // tokens per sequence
#define NHEAD  32
#define HDIM   128
#define NBATCH 4

// Scratch (allocation-free rule: __device__ globals). Referenced directly in
// device code — no cudaGetSymbolAddress in kernel_launch (capture safety).
__device__ float g_qkv[3LL * T_TOK * HID];          // [3][T][H]
__device__ float g_attn[(long long)T_TOK * HID];    // [T][H]

// ---------------------------------------------------------------------------
// TF32 helpers
// ---------------------------------------------------------------------------
__device__ __forceinline__ float to_tf32(float x) {
    unsigned u;
    asm("cvt.rna.tf32.f32 %0, %1;" : "=r"(u) : "f"(x));
    return __uint_as_float(u);
}

__device__ __forceinline__ void mma8(float d[4], const unsigned a[4], const unsigned b[2]) {
    asm volatile(
        "mma.sync.aligned.m16n8k8.row.col.f32.tf32.tf32.f32 "
        "{%0,%1,%2,%3}, {%4,%5,%6,%7}, {%8,%9}, {%0,%1,%2,%3};"
        : "+f"(d[0]), "+f"(d[1]), "+f"(d[2]), "+f"(d[3])
        : "r"(a[0]), "r"(a[1]), "r"(a[2]), "r"(a[3]), "r"(b[0]), "r"(b[1]));
}

// ---------------------------------------------------------------------------
// TF32 GEMM: C[M,N] = A[M,K] @ B[K,N], row-major. K = HID, N = HID, M = T_TOK.
// Block tile 128x128, K-tile 32, 256 threads (8 warps 4x2, warp tile 32x64).
// Register-staged prefetch: load tile t+1 into regs while computing tile t.
// MODE 0: A = Aarg (hidden_states), B = qkv_w + z*H*H, C = g_qkv + z*T*H
// MODE 1: A = g_attn,               B = o_proj_w,      C = Carg (d_out)
// ---------------------------------------------------------------------------
template<int MODE>
__global__ __launch_bounds__(256) void gemm_tf32_kernel(
    const float* __restrict__ Aarg, const float* __restrict__ Bg, float* __restrict__ Carg)
{
    const long long HH = (long long)HID * HID;
    const long long TH = (long long)T_TOK * HID;
    const float* A;
    const float* B;
    float*       C;
    if (MODE == 0) {
        A = Aarg;
        B = Bg + (long long)blockIdx.z * HH;
        C = g_qkv + (long long)blockIdx.z * TH;
    } else {
        A = g_attn;
        B = Bg;
        C = Carg;
    }
    const int K = HID, N = HID;

    __shared__ float As[128][36];    // pad 4: conflict-free A fragment loads
    __shared__ float Bs[32][132];    // pad 4: <=2-way on B fragment loads

    const int tid  = threadIdx.x;
    const int lane = tid & 31;
    const int grp  = lane >> 2;      // 0..7
    const int qd   = lane & 3;       // 0..3
    const int warp = tid >> 5;
    const int wm   = (warp & 3) * 32;
    const int wn   = (warp >> 2) * 64;
    const int bm   = blockIdx.y * 128;
    const int bn   = blockIdx.x * 128;

    // Per-thread staging coordinates (fixed across tiles)
    const int ar = tid >> 3;              // A row within tile, +32 per i
    const int ac = (tid & 7) << 2;        // A col (float4)
    const int br = tid >> 5;              // B row within tile, +8 per i
    const int bc = (tid & 31) << 2;       // B col (float4)

    float4 aReg[4], bReg[4];

    auto load_regs = [&](int kt) {
        #pragma unroll
        for (int i = 0; i < 4; i++)
            aReg[i] = *reinterpret_cast<const float4*>(
                A + (long long)(bm + ar + i * 32) * K + kt + ac);
        #pragma unroll
        for (int i = 0; i < 4; i++)
            bReg[i] = *reinterpret_cast<const float4*>(
                B + (long long)(kt + br + i * 8) * N + bn + bc);
    };
    auto store_regs = [&]() {
        #pragma unroll
        for (int i = 0; i < 4; i++) {
            int r = ar + i * 32;
            As[r][ac + 0] = to_tf32(aReg[i].x);
            As[r][ac + 1] = to_tf32(aReg[i].y);
            As[r][ac + 2] = to_tf32(aReg[i].z);
            As[r][ac + 3] = to_tf32(aReg[i].w);
        }
        #pragma unroll
        for (int i = 0; i < 4; i++) {
            int r = br + i * 8;
            Bs[r][bc + 0] = to_tf32(bReg[i].x);
            Bs[r][bc + 1] = to_tf32(bReg[i].y);
            Bs[r][bc + 2] = to_tf32(bReg[i].z);
            Bs[r][bc + 3] = to_tf32(bReg[i].w);
        }
    };

    float acc[2][8][4];
    #pragma unroll
    for (int i = 0; i < 2; i++)
        #pragma unroll
        for (int j = 0; j < 8; j++)
            #pragma unroll
            for (int l = 0; l < 4; l++) acc[i][j][l] = 0.f;

    // Prologue: stage tile 0
    load_regs(0);
    store_regs();
    __syncthreads();

    for (int kt = 0; kt < K; kt += 32) {
        const bool more = (kt + 32) < K;
        if (more) load_regs(kt + 32);   // overlap next-tile loads with compute

        #pragma unroll
        for (int kk = 0; kk < 32; kk += 8) {
            unsigned af[2][4], bf[8][2];
            #pragma unroll
            for (int mi = 0; mi < 2; mi++) {
                int r = wm + mi * 16 + grp;
                af[mi][0] = __float_as_uint(As[r][kk + qd]);
                af[mi][1] = __float_as_uint(As[r + 8][kk + qd]);
                af[mi][2] = __float_as_uint(As[r][kk + qd + 4]);
                af[mi][3] = __float_as_uint(As[r + 8][kk + qd + 4]);
            }
            #pragma unroll
            for (int ni = 0; ni < 8; ni++) {
                int c = wn + ni * 8 + grp;
                bf[ni][0] = __float_as_uint(Bs[kk + qd][c]);
                bf[ni][1] = __float_as_uint(Bs[kk + qd + 4][c]);
            }
            #pragma unroll
            for (int mi = 0; mi < 2; mi++)
                #pragma unroll
                for (int ni = 0; ni < 8; ni++)
                    mma8(acc[mi][ni], af[mi], bf[ni]);
        }
        __syncthreads();
        if (more) {
            store_regs();
            __syncthreads();
        }
    }

    // Epilogue: c0/c1 and c2/c3 are adjacent columns -> float2 stores
    #pragma unroll
    for (int mi = 0; mi < 2; mi++) {
        #pragma unroll
        for (int ni = 0; ni < 8; ni++) {
            int r0 = bm + wm + mi * 16 + grp;
            int c0 = bn + wn + ni * 8 + (qd << 1);
            float2 v0 = make_float2(acc[mi][ni][0], acc[mi][ni][1]);
            float2 v1 = make_float2(acc[mi][ni][2], acc[mi][ni][3]);
            *reinterpret_cast<float2*>(C + (long long)r0 * N + c0)       = v0;
            *reinterpret_cast<float2*>(C + (long long)(r0 + 8) * N + c0) = v1;
        }
    }
}

// ---------------------------------------------------------------------------
// FP32 flash attention with ALiBi + causal mask. Reads g_qkv, writes g_attn.
// Grid: (S/16, NH, B). Block: 256 threads.
// Thread (qi = tid/16, u = tid%16): scores for kj in {u, u+16, u+32, u+48} of
// its query row; owns output columns {4u..4u+3, 64+4u..64+4u+3}.
// K and V share one smem tile (sequential loads) to stay < 48KB static.
// ---------------------------------------------------------------------------
__device__ __forceinline__ long long tok_off(int b, int s) {
    return ((long long)(b * SEQ + s)) * HID;
}

__global__ __launch_bounds__(256) void attn_kernel(const int* __restrict__ seqlens)
{
    const int qb = blockIdx.x;
    const int h  = blockIdx.y;
    const int b  = blockIdx.z;
    const int q0 = qb * 16;
    const int seqlen = seqlens[b];

    __shared__ float Qs[16][HDIM + 4];
    __shared__ float KV[64][HDIM + 4];
    __shared__ float Ps[16][68];

    const int tid = threadIdx.x;
    const int qi  = tid >> 4;
    const int u   = tid & 15;
    const int qg  = q0 + qi;

    const float* Qbase = g_qkv;
    const float* Kbase = g_qkv + (long long)T_TOK * HID;
    const float* Vbase = g_qkv + 2LL * T_TOK * HID;

    // Load Q tile 16x128
    #pragma unroll
    for (int i = 0; i < 2; i++) {
        int idx = tid + i * 256;
        int r = idx >> 5;
        int c = (idx & 31) << 2;
        *reinterpret_cast<float4*>(&Qs[r][c]) =
            *reinterpret_cast<const float4*>(Qbase + tok_off(b, q0 + r) + h * HDIM + c);
    }

    const float sm_scale = 0.08838834764831845f;          // 1/sqrt(128)
    const float slope = exp2f(-0.25f * (float)(h + 1));   // Bloom ALiBi, NH=32 (pow2)
    float m_run = -1e30f, l_run = 0.f;
    float4 o0 = make_float4(0.f, 0.f, 0.f, 0.f);
    float4 o1 = make_float4(0.f, 0.f, 0.f, 0.f);

    const int nkv = (q0 + 16 + 63) >> 6;   // causal: skip fully-masked key blocks

    for (int kb = 0; kb < nkv; kb++) {
        const int k0b = kb << 6;

        __syncthreads();   // previous PV done (and Q load visible on kb==0)
        // Load K tile 64x128
        #pragma unroll
        for (int i = 0; i < 8; i++) {
            int idx = tid + i * 256;
            int r = idx >> 5;
            int c = (idx & 31) << 2;
            *reinterpret_cast<float4*>(&KV[r][c]) =
                *reinterpret_cast<const float4*>(Kbase + tok_off(b, k0b + r) + h * HDIM + c);
        }
        __syncthreads();

        // Scores: 4 dot products of length 128 per thread
        float sc0 = 0.f, sc1 = 0.f, sc2 = 0.f, sc3 = 0.f;
        #pragma unroll 8
        for (int d4 = 0; d4 < 32; d4++) {
            float4 qv = *reinterpret_cast<const float4*>(&Qs[qi][d4 << 2]);
            float4 k0 = *reinterpret_cast<const float4*>(&KV[u][d4 << 2]);
            float4 k1 = *reinterpret_cast<const float4*>(&KV[u + 16][d4 << 2]);
            float4 k2 = *reinterpret_cast<const float4*>(&KV[u + 32][d4 << 2]);
            float4 k3 = *reinterpret_cast<const float4*>(&KV[u + 48][d4 << 2]);
            sc0 += qv.x * k0.x + qv.y * k0.y + qv.z * k0.z + qv.w * k0.w;
            sc1 += qv.x * k1.x + qv.y * k1.y + qv.z * k1.z + qv.w * k1.w;
            sc2 += qv.x * k2.x + qv.y * k2.y + qv.z * k2.z + qv.w * k2.w;
            sc3 += qv.x * k3.x + qv.y * k3.y + qv.z * k3.z + qv.w * k3.w;
        }
        float sc[4] = {sc0, sc1, sc2, sc3};

        float tmax = -1e30f;
        #pragma unroll
        for (int j = 0; j < 4; j++) {
            int kg = k0b + u + 16 * j;
            float s = sc[j] * sm_scale + slope * (float)(kg - qg);
            if (kg > qg || kg >= seqlen) s = -1e30f;
            sc[j] = s;
            tmax = fmaxf(tmax, s);
        }
        // Row reduce over the 16 lanes owning this query row (contiguous lanes)
        #pragma unroll
        for (int o = 8; o > 0; o >>= 1)
            tmax = fmaxf(tmax, __shfl_xor_sync(0xffffffffu, tmax, o, 16));

        float m_new = fmaxf(m_run, tmax);
        float rescale = __expf(m_run - m_new);
        float lsum = 0.f;
        #pragma unroll
        for (int j = 0; j < 4; j++) {
            float p = __expf(sc[j] - m_new);
            Ps[qi][u + 16 * j] = p;
            lsum += p;
        }
        #pragma unroll
        for (int o = 8; o > 0; o >>= 1)
            lsum += __shfl_xor_sync(0xffffffffu, lsum, o, 16);

        l_run = l_run * rescale + lsum;
        m_run = m_new;
        o0.x *= rescale; o0.y *= rescale; o0.z *= rescale; o0.w *= rescale;
        o1.x *= rescale; o1.y *= rescale; o1.z *= rescale; o1.w *= rescale;

        __syncthreads();   // everyone done reading K (and Ps visible block-wide)
        // Load V tile 64x128 into the same buffer
        #pragma unroll
        for (int i = 0; i < 8; i++) {
            int idx = tid + i * 256;
            int r = idx >> 5;
            int c = (idx & 31) << 2;
            *reinterpret_cast<float4*>(&KV[r][c]) =
                *reinterpret_cast<const float4*>(Vbase + tok_off(b, k0b + r) + h * HDIM + c);
        }
        __syncthreads();

        // PV: out[qi][cols] += sum_kj P[qi][kj] * V[kj][cols]
        #pragma unroll 4
        for (int kj = 0; kj < 64; kj++) {
            float p = Ps[qi][kj];
            float4 v0 = *reinterpret_cast<const float4*>(&KV[kj][u << 2]);
            float4 v1 = *reinterpret_cast<const float4*>(&KV[kj][64 + (u << 2)]);
            o0.x += p * v0.x; o0.y += p * v0.y; o0.z += p * v0.z; o0.w += p * v0.w;
            o1.x += p * v1.x; o1.y += p * v1.y; o1.z += p * v1.z; o1.w += p * v1.w;
        }
    }

    float inv = 1.0f / l_run;
    o0.x *= inv; o0.y *= inv; o0.z *= inv; o0.w *= inv;
    o1.x *= inv; o1.y *= inv; o1.z *= inv; o1.w *= inv;

    float* orow = g_attn + tok_off(b, qg) + h * HDIM;
    *reinterpret_cast<float4*>(orow + (u << 2))      = o0;
    *reinterpret_cast<float4*>(orow + 64 + (u << 2)) = o1;
}

// ---------------------------------------------------------------------------
// Launch: QKV GEMM (batched z=3) -> attention -> O-proj GEMM.
// Pure kernel launches — nothing else (graph-capture safety).
// ---------------------------------------------------------------------------
extern "C" void kernel_launch(void* const* d_in, const int* in_sizes, int n_in,
                              void* d_out, int out_size) {
    const float* hs = (const float*)d_in[0];   // [T, H]
    const float* qw = (const float*)d_in[1];   // [3, H, H]
    const float* ow = (const float*)d_in[2];   // [H, H]
    const int* seq  = (const int*)d_in[3];     // [B]
    float* out = (float*)d_out;                // [T, H]

    dim3 block(256);

    dim3 g1(HID / 128, T_TOK / 128, 3);
    gemm_tf32_kernel<0><<<g1, block>>>(hs, qw, nullptr);

    dim3 g2(SEQ / 16, NHEAD, NBATCH);
    attn_kernel<<<g2, block>>>(seq);

    dim3 g3(HID / 128, T_TOK / 128, 1);
    gemm_tf32_kernel<1><<<g3, block>>>(nullptr, ow, out);
}

// round 3
// speedup vs baseline: 1.1217x; 1.1217x over previous
#include <cuda_runtime.h>
#include <math.h>

// Problem constants (fixed by the dataset)
#define T_TOK  4096     // B * S
#define HID    4096     // hidden
#define SEQ    1024     // tokens per sequence
#define NHEAD  32
#define HDIM   128
#define NBATCH 4

// Scratch (allocation-free rule: __device__ globals)
__device__ float g_qkv[3LL * T_TOK * HID];          // [3][T][H]
__device__ float g_attn[(long long)T_TOK * HID];    // [T][H]

// ---------------------------------------------------------------------------
// TF32 helpers
// ---------------------------------------------------------------------------
__device__ __forceinline__ float to_tf32(float x) {
    unsigned u;
    asm("cvt.rna.tf32.f32 %0, %1;" : "=r"(u) : "f"(x));
    return __uint_as_float(u);
}

__device__ __forceinline__ void mma8(float d[4], const unsigned a[4], const unsigned b[2]) {
    asm volatile(
        "mma.sync.aligned.m16n8k8.row.col.f32.tf32.tf32.f32 "
        "{%0,%1,%2,%3}, {%4,%5,%6,%7}, {%8,%9}, {%0,%1,%2,%3};"
        : "+f"(d[0]), "+f"(d[1]), "+f"(d[2]), "+f"(d[3])
        : "r"(a[0]), "r"(a[1]), "r"(a[2]), "r"(a[3]), "r"(b[0]), "r"(b[1]));
}

// Fragment-layout conventions (m16n8k8, validated by the passing round-2 kernel):
//   A element (m,k): lane = (m&7)*4 + (k&3), reg = ((m>>3)&1) + 2*((k&7)>>2)
//   B element (k,n): lane = (n&7)*4 + (k&3), reg = (k&7)>>2
//   C: c0,c1 = row grp, cols 2qd,2qd+1 ; c2,c3 = row grp+8
// A tiles stored as float4 per lane, B tiles as float2 per lane; each 32-lane
// block padded by 1 element (33 stride) to stagger banks.

// ---------------------------------------------------------------------------
// TF32 GEMM: C[M,N] = A[M,K] @ B[K,N]. Block 128x128, K-tile 32, 256 threads,
// 8 warps (4 m-tiles of 32 x 2 n-tiles of 64). Fragment-swizzled smem: inner
// loop does 2 LDS.128 + 8 LDS.64 + 16 mma per k-slice. Register prefetch of
// the next tile overlaps global latency with compute.
// MODE 0: A = hidden_states, B = qkv_w + z*H*H, C = g_qkv + z*T*H
// MODE 1: A = g_attn,        B = o_proj_w,      C = d_out
// ---------------------------------------------------------------------------
template<int MODE>
__global__ __launch_bounds__(256) void gemm_tf32_kernel(
    const float* __restrict__ Aarg, const float* __restrict__ Bg, float* __restrict__ Carg)
{
    const long long HH = (long long)HID * HID;
    const long long TH = (long long)T_TOK * HID;
    const float* A;
    const float* B;
    float*       C;
    if (MODE == 0) {
        A = Aarg;
        B = Bg + (long long)blockIdx.z * HH;
        C = g_qkv + (long long)blockIdx.z * TH;
    } else {
        A = g_attn;
        B = Bg;
        C = Carg;
    }
    const int K = HID, N = HID;

    // A frags: blocks (kb 0..3)*(rb 0..7), 33 float4 per block
    __shared__ float4 AF4[4 * 8 * 33];
    // B frags: blocks (kb 0..3)*(nb 0..15), 33 float2 per block
    __shared__ float2 BF2[4 * 16 * 33];
    float* Af = reinterpret_cast<float*>(AF4);
    float* Bf = reinterpret_cast<float*>(BF2);

    const int tid  = threadIdx.x;
    const int lane = tid & 31;
    const int grp  = lane >> 2;
    const int qd   = lane & 3;
    const int warp = tid >> 5;
    const int wm   = (warp & 3) * 32;
    const int wn   = (warp >> 2) * 64;
    const int rb0  = (warp & 3) * 2;     // A row-block base (two m16 blocks)
    const int nb0  = (warp >> 2) * 8;    // B n-block base (eight n8 blocks)
    const int bm   = blockIdx.y * 128;
    const int bn   = blockIdx.x * 128;

    // Staging coordinates
    const int ar = tid >> 3;             // A rows ar + i*32
    const int ac = (tid & 7) << 2;       // A cols (within 32-wide k-tile)
    const int br = tid >> 5;             // B rows br + i*8
    const int bc = (tid & 31) << 2;      // B cols (within 128-wide n-tile)
    const int kbA   = ac >> 3;
    const int halfA = (ac >> 2) & 1;
    const int nbB   = bc >> 3;
    const int n7B   = bc & 7;

    float4 aReg[4], bReg[4];

    auto load_regs = [&](int kt) {
        #pragma unroll
        for (int i = 0; i < 4; i++)
            aReg[i] = *reinterpret_cast<const float4*>(
                A + (long long)(bm + ar + i * 32) * K + kt + ac);
        #pragma unroll
        for (int i = 0; i < 4; i++)
            bReg[i] = *reinterpret_cast<const float4*>(
                B + (long long)(kt + br + i * 8) * N + bn + bc);
    };
    auto store_regs = [&]() {
        #pragma unroll
        for (int i = 0; i < 4; i++) {
            int r   = ar + i * 32;
            int rb  = r >> 4;
            int gs  = r & 7;
            int top = (r >> 3) & 1;
            int reg = top + 2 * halfA;
            int base = ((kbA * 8 + rb) * 33 + gs * 4) * 4 + reg;
            Af[base +  0] = to_tf32(aReg[i].x);
            Af[base +  4] = to_tf32(aReg[i].y);
            Af[base +  8] = to_tf32(aReg[i].z);
            Af[base + 12] = to_tf32(aReg[i].w);
        }
        #pragma unroll
        for (int i = 0; i < 4; i++) {
            int k   = br + i * 8;
            int kb  = k >> 3;
            int kk7 = k & 7;
            int qds = kk7 & 3;
            int reg = kk7 >> 2;
            int base = ((kb * 16 + nbB) * 33 + n7B * 4 + qds) * 2 + reg;
            Bf[base +  0] = to_tf32(bReg[i].x);
            Bf[base +  8] = to_tf32(bReg[i].y);
            Bf[base + 16] = to_tf32(bReg[i].z);
            Bf[base + 24] = to_tf32(bReg[i].w);
        }
    };

    float acc[2][8][4];
    #pragma unroll
    for (int i = 0; i < 2; i++)
        #pragma unroll
        for (int j = 0; j < 8; j++)
            #pragma unroll
            for (int l = 0; l < 4; l++) acc[i][j][l] = 0.f;

    load_regs(0);
    store_regs();
    __syncthreads();

    for (int kt = 0; kt < K; kt += 32) {
        const bool more = (kt + 32) < K;
        if (more) load_regs(kt + 32);

        #pragma unroll
        for (int kb = 0; kb < 4; kb++) {
            float4 a0 = AF4[(kb * 8 + rb0)     * 33 + lane];
            float4 a1 = AF4[(kb * 8 + rb0 + 1) * 33 + lane];
            unsigned af[2][4] = {
                {__float_as_uint(a0.x), __float_as_uint(a0.y), __float_as_uint(a0.z), __float_as_uint(a0.w)},
                {__float_as_uint(a1.x), __float_as_uint(a1.y), __float_as_uint(a1.z), __float_as_uint(a1.w)}};
            unsigned bfr[8][2];
            #pragma unroll
            for (int ni = 0; ni < 8; ni++) {
                float2 bv = BF2[(kb * 16 + nb0 + ni) * 33 + lane];
                bfr[ni][0] = __float_as_uint(bv.x);
                bfr[ni][1] = __float_as_uint(bv.y);
            }
            #pragma unroll
            for (int mi = 0; mi < 2; mi++)
                #pragma unroll
                for (int ni = 0; ni < 8; ni++)
                    mma8(acc[mi][ni], af[mi], bfr[ni]);
        }
        __syncthreads();
        if (more) {
            store_regs();
            __syncthreads();
        }
    }

    #pragma unroll
    for (int mi = 0; mi < 2; mi++) {
        #pragma unroll
        for (int ni = 0; ni < 8; ni++) {
            int r0 = bm + wm + mi * 16 + grp;
            int c0 = bn + wn + ni * 8 + (qd << 1);
            float2 v0 = make_float2(acc[mi][ni][0], acc[mi][ni][1]);
            float2 v1 = make_float2(acc[mi][ni][2], acc[mi][ni][3]);
            *reinterpret_cast<float2*>(C + (long long)r0 * N + c0)       = v0;
            *reinterpret_cast<float2*>(C + (long long)(r0 + 8) * N + c0) = v1;
        }
    }
}

// ---------------------------------------------------------------------------
// Tensor-core flash attention (tf32 mma for scores and PV), ALiBi + causal.
// Q-tile 32, K-tile 32. Grid: (S/32, NH, B). Block: 256 threads, 8 warps.
// Scores:  warp = (rb 0..1) x (nb 0..3):  S[16x8] tile over k=128
// PV:      warp = (rb 0..1) x (nb32 0..3): O[16x32] tile over k=32
// Q, K, V, P all staged in mma fragment layout. K and V share one buffer.
// ---------------------------------------------------------------------------
__global__ __launch_bounds__(256) void attn_kernel(const int* __restrict__ seqlens)
{
    const int h  = blockIdx.y;
    const int b  = blockIdx.z;
    const int q0 = blockIdx.x * 32;
    const int seqlen = seqlens[b];

    __shared__ float4 QF4[16 * 2 * 33];    // Q frags: (kb 0..15 d)*(rb 0..1)
    __shared__ float2 KVF2[64 * 33];       // K: (kb 0..15 d)*(nb 0..3 key) | V: (kb 0..3 key)*(nb 0..15 d)
    __shared__ float4 PF4[4 * 2 * 33];     // P frags: (kb 0..3 key)*(rb 0..1)
    __shared__ float m_run[32], l_run[32], resc[32];
    __shared__ float redm[32][4];
    __shared__ float reds[32][4];
    float* Qf = reinterpret_cast<float*>(QF4);
    float* KVf = reinterpret_cast<float*>(KVF2);
    float* Pf = reinterpret_cast<float*>(PF4);

    const int tid  = threadIdx.x;
    const int lane = tid & 31;
    const int grp  = lane >> 2;
    const int qd   = lane & 3;
    const int warp = tid >> 5;
    const int rbw  = warp >> 2;       // 0..1 (query 16-row block)
    const int nbw  = warp & 3;        // 0..3 (scores: key 8-block; PV: d 32-block)

    const float* Qbase = g_qkv;
    const float* Kbase = g_qkv + (long long)T_TOK * HID;
    const float* Vbase = g_qkv + 2LL * T_TOK * HID;

    // Staging coords: row = tid>>3 (0..31), 4 float4 per row at (tid&7)*4 + i*32
    const int srow  = tid >> 3;
    const int scol  = (tid & 7) << 2;

    if (tid < 32) { m_run[tid] = -1e30f; l_run[tid] = 0.f; }

    // Stage Q (32 x 128) into A-fragment layout
    {
        const float* qp = Qbase + (long long)(b * SEQ + q0 + srow) * HID + h * HDIM;
        int rb = srow >> 4, gs = srow & 7, top = (srow >> 3) & 1;
        #pragma unroll
        for (int i = 0; i < 4; i++) {
            int c = scol + i * 32;
            float4 v = *reinterpret_cast<const float4*>(qp + c);
            int kb = c >> 3, half = (c >> 2) & 1, reg = top + 2 * half;
            int base = ((kb * 2 + rb) * 33 + gs * 4) * 4 + reg;
            Qf[base +  0] = to_tf32(v.x);
            Qf[base +  4] = to_tf32(v.y);
            Qf[base +  8] = to_tf32(v.z);
            Qf[base + 12] = to_tf32(v.w);
        }
    }

    const float sm_scale = 0.08838834764831845f;          // 1/sqrt(128)
    const float slope = exp2f(-0.25f * (float)(h + 1));   // Bloom ALiBi, NH=32

    float o[4][4];
    #pragma unroll
    for (int t = 0; t < 4; t++)
        #pragma unroll
        for (int l = 0; l < 4; l++) o[t][l] = 0.f;

    const int r0 = rbw * 16 + grp;
    const int r1 = r0 + 8;
    const int qg0 = q0 + r0;
    const int qg1 = q0 + r1;

    const int ntiles = (q0 >> 5) + 1;

    for (int tile = 0; tile < ntiles; tile++) {
        const int k0 = tile << 5;

        __syncthreads();   // prior PV reads of KVF/PF done; Q staged (tile 0)

        // Stage K tile (32 keys x 128 d) into scores-B fragment layout
        {
            const float* kp = Kbase + (long long)(b * SEQ + k0 + srow) * HID + h * HDIM;
            int nb = srow >> 3;
            int lanebase = (srow & 7) * 4;
            #pragma unroll
            for (int i = 0; i < 4; i++) {
                int c = scol + i * 32;
                float4 v = *reinterpret_cast<const float4*>(kp + c);
                int kb = c >> 3, reg = (c >> 2) & 1;
                int base = ((kb * 4 + nb) * 33 + lanebase) * 2 + reg;
                KVf[base + 0] = to_tf32(v.x);
                KVf[base + 2] = to_tf32(v.y);
                KVf[base + 4] = to_tf32(v.z);
                KVf[base + 6] = to_tf32(v.w);
            }
        }
        __syncthreads();

        // Scores mma: warp tile 16(q) x 8(key), k = 128
        float sacc[4] = {0.f, 0.f, 0.f, 0.f};
        #pragma unroll
        for (int kb = 0; kb < 16; kb++) {
            float4 a = QF4[(kb * 2 + rbw) * 33 + lane];
            float2 bv = KVF2[(kb * 4 + nbw) * 33 + lane];
            unsigned af[4] = {__float_as_uint(a.x), __float_as_uint(a.y),
                              __float_as_uint(a.z), __float_as_uint(a.w)};
            unsigned bf[2] = {__float_as_uint(bv.x), __float_as_uint(bv.y)};
            mma8(sacc, af, bf);
        }

        // Scale + ALiBi + mask
        const int kl = nbw * 8 + qd * 2;
        const int kg0 = k0 + kl, kg1 = kg0 + 1;
        float s00 = sacc[0] * sm_scale + slope * (float)(kg0 - qg0);
        float s01 = sacc[1] * sm_scale + slope * (float)(kg1 - qg0);
        float s10 = sacc[2] * sm_scale + slope * (float)(kg0 - qg1);
        float s11 = sacc[3] * sm_scale + slope * (float)(kg1 - qg1);
        if (kg0 > qg0 || kg0 >= seqlen) s00 = -1e30f;
        if (kg1 > qg0 || kg1 >= seqlen) s01 = -1e30f;
        if (kg0 > qg1 || kg0 >= seqlen) s10 = -1e30f;
        if (kg1 > qg1 || kg1 >= seqlen) s11 = -1e30f;

        // Row max: reduce over qd lanes, then cross-warp via smem
        float mx0 = fmaxf(s00, s01);
        float mx1 = fmaxf(s10, s11);
        mx0 = fmaxf(mx0, __shfl_xor_sync(0xffffffffu, mx0, 1));
        mx0 = fmaxf(mx0, __shfl_xor_sync(0xffffffffu, mx0, 2));
        mx1 = fmaxf(mx1, __shfl_xor_sync(0xffffffffu, mx1, 1));
        mx1 = fmaxf(mx1, __shfl_xor_sync(0xffffffffu, mx1, 2));
        if (qd == 0) { redm[r0][nbw] = mx0; redm[r1][nbw] = mx1; }
        __syncthreads();

        if (tid < 32) {
            float mt = fmaxf(fmaxf(redm[tid][0], redm[tid][1]),
                             fmaxf(redm[tid][2], redm[tid][3]));
            float mn = fmaxf(m_run[tid], mt);
            resc[tid] = __expf(m_run[tid] - mn);
            m_run[tid] = mn;
        }
        __syncthreads();

        // P = exp(s - m_new), store into PV-A fragment layout (tf32)
        {
            float mn0 = m_run[r0], mn1 = m_run[r1];
            float p00 = __expf(s00 - mn0);
            float p01 = __expf(s01 - mn0);
            float p10 = __expf(s10 - mn1);
            float p11 = __expf(s11 - mn1);

            int qp0 = (2 * qd) & 3, qp1 = (2 * qd + 1) & 3;
            int hh  = qd >> 1;
            int pbase = ((nbw * 2 + rbw) * 33 + grp * 4) * 4;
            Pf[pbase + qp0 * 4 + 2 * hh]     = to_tf32(p00);
            Pf[pbase + qp1 * 4 + 2 * hh]     = to_tf32(p01);
            Pf[pbase + qp0 * 4 + 2 * hh + 1] = to_tf32(p10);
            Pf[pbase + qp1 * 4 + 2 * hh + 1] = to_tf32(p11);

            float sum0 = p00 + p01;
            float sum1 = p10 + p11;
            sum0 += __shfl_xor_sync(0xffffffffu, sum0, 1);
            sum0 += __shfl_xor_sync(0xffffffffu, sum0, 2);
            sum1 += __shfl_xor_sync(0xffffffffu, sum1, 1);
            sum1 += __shfl_xor_sync(0xffffffffu, sum1, 2);
            if (qd == 0) { reds[r0][nbw] = sum0; reds[r1][nbw] = sum1; }
        }

        // Stage V tile (32 keys x 128 d) into PV-B fragment layout (reuses KVF)
        {
            const float* vp = Vbase + (long long)(b * SEQ + k0 + srow) * HID + h * HDIM;
            int kbV = srow >> 3;
            int qdV = srow & 3;
            int regV = (srow & 7) >> 2;
            #pragma unroll
            for (int i = 0; i < 4; i++) {
                int c = scol + i * 32;
                float4 v = *reinterpret_cast<const float4*>(vp + c);
                int nb = c >> 3;
                int base = ((kbV * 16 + nb) * 33 + (c & 7) * 4 + qdV) * 2 + regV;
                KVf[base +  0] = to_tf32(v.x);
                KVf[base +  8] = to_tf32(v.y);
                KVf[base + 16] = to_tf32(v.z);
                KVf[base + 24] = to_tf32(v.w);
            }
        }
        __syncthreads();

        if (tid < 32)
            l_run[tid] = l_run[tid] * resc[tid] +
                         (reds[tid][0] + reds[tid][1] + reds[tid][2] + reds[tid][3]);

        // PV mma: warp tile 16(q) x 32(d), k = 32 keys
        {
            float f0 = resc[r0], f1 = resc[r1];
            #pragma unroll
            for (int t = 0; t < 4; t++) {
                o[t][0] *= f0; o[t][1] *= f0;
                o[t][2] *= f1; o[t][3] *= f1;
            }
            #pragma unroll
            for (int kb = 0; kb < 4; kb++) {
                float4 a = PF4[(kb * 2 + rbw) * 33 + lane];
                unsigned af[4] = {__float_as_uint(a.x), __float_as_uint(a.y),
                                  __float_as_uint(a.z), __float_as_uint(a.w)};
                #pragma unroll
                for (int t = 0; t < 4; t++) {
                    float2 bv = KVF2[(kb * 16 + nbw * 4 + t) * 33 + lane];
                    unsigned bf[2] = {__float_as_uint(bv.x), __float_as_uint(bv.y)};
                    mma8(o[t], af, bf);
                }
            }
        }
    }

    __syncthreads();
    {
        float inv0 = 1.0f / l_run[r0];
        float inv1 = 1.0f / l_run[r1];
        float* out0 = g_attn + (long long)(b * SEQ + qg0) * HID + h * HDIM;
        float* out1 = g_attn + (long long)(b * SEQ + qg1) * HID + h * HDIM;
        #pragma unroll
        for (int t = 0; t < 4; t++) {
            int d = (nbw * 4 + t) * 8 + (qd << 1);
            *reinterpret_cast<float2*>(out0 + d) = make_float2(o[t][0] * inv0, o[t][1] * inv0);
            *reinterpret_cast<float2*>(out1 + d) = make_float2(o[t][2] * inv1, o[t][3] * inv1);
        }
    }
}

// ---------------------------------------------------------------------------
// Launch: QKV GEMM (batched z=3) -> attention -> O-proj GEMM
// ---------------------------------------------------------------------------
extern "C" void kernel_launch(void* const* d_in, const int* in_sizes, int n_in,
                              void* d_out, int out_size) {
    const float* hs = (const float*)d_in[0];   // [T, H]
    const float* qw = (const float*)d_in[1];   // [3, H, H]
    const float* ow = (const float*)d_in[2];   // [H, H]
    const int* seq  = (const int*)d_in[3];     // [B]
    float* out = (float*)d_out;                // [T, H]

    dim3 block(256);

    dim3 g1(HID / 128, T_TOK / 128, 3);
    gemm_tf32_kernel<0><<<g1, block>>>(hs, qw, nullptr);

    dim3 g2(SEQ / 32, NHEAD, NBATCH);
    attn_kernel<<<g2, block>>>(seq);

    dim3 g3(HID / 128, T_TOK / 128, 1);
    gemm_tf32_kernel<1><<<g3, block>>>(nullptr, ow, out);
}